// round 4
// baseline (speedup 1.0000x reference)
#include <cuda_runtime.h>

// Problem constants (fixed by the dataset)
#define NN   100000
#define EE   3200000
#define FF   7
#define HH   128
#define DD   64
#define EPSV 1e-5f

#define SCAN_BS 1024
#define NBLK ((NN + SCAN_BS - 1) / SCAN_BS)

// ---------------- device scratch (static; no allocations) ----------------
__device__ float g_A[NN * HH];     // node features (h / h0 / h1, in-place residual)
__device__ float g_B[NN * HH];     // per-layer X@W scratch (used as N x DO)
__device__ float g_dinv[NN];
__device__ int   g_cnt[NN];
__device__ int   g_rowptr[NN + 1];
__device__ int   g_fill[NN];
__device__ int   g_esrc[EE];
__device__ float g_ecoef[EE];
__device__ int   g_blksums[NBLK];

// ---------------- CSR build ----------------
__global__ void k_zero_cnt() {
    for (int i = blockIdx.x * blockDim.x + threadIdx.x; i < NN; i += gridDim.x * blockDim.x)
        g_cnt[i] = 0;
}

// edge_index is int32 (JAX x64 disabled: jnp.int64 request silently yields int32)
__global__ void k_hist(const int* __restrict__ ei) {
    for (int e = blockIdx.x * blockDim.x + threadIdx.x; e < EE; e += gridDim.x * blockDim.x) {
        int d = ei[EE + e];
        atomicAdd(&g_cnt[d], 1);
    }
}

__global__ void k_dinv() {
    int i = blockIdx.x * blockDim.x + threadIdx.x;
    if (i < NN) g_dinv[i] = rsqrtf((float)g_cnt[i] + 1.0f);
}

__global__ void k_scan_local() {
    __shared__ int sh[SCAN_BS];
    int tid = threadIdx.x;
    int i = blockIdx.x * SCAN_BS + tid;
    int v = (i < NN) ? g_cnt[i] : 0;
    sh[tid] = v;
    __syncthreads();
    for (int off = 1; off < SCAN_BS; off <<= 1) {
        int t = (tid >= off) ? sh[tid - off] : 0;
        __syncthreads();
        sh[tid] += t;
        __syncthreads();
    }
    if (i < NN) g_rowptr[i] = sh[tid] - v;  // exclusive prefix within block
    if (tid == SCAN_BS - 1) g_blksums[blockIdx.x] = sh[tid];
}

__global__ void k_scan_blocks() {
    if (threadIdx.x == 0 && blockIdx.x == 0) {
        int run = 0;
        for (int b = 0; b < NBLK; b++) {
            int t = g_blksums[b];
            g_blksums[b] = run;
            run += t;
        }
    }
}

__global__ void k_scan_add() {
    int i = blockIdx.x * SCAN_BS + threadIdx.x;
    if (i < NN) {
        int r = g_rowptr[i] + g_blksums[blockIdx.x];
        g_rowptr[i] = r;
        g_fill[i] = r;
    }
    if (i == 0) g_rowptr[NN] = EE;
}

__global__ void k_scatter(const int* __restrict__ ei) {
    for (int e = blockIdx.x * blockDim.x + threadIdx.x; e < EE; e += gridDim.x * blockDim.x) {
        int s = ei[e];
        int d = ei[EE + e];
        int pos = atomicAdd(&g_fill[d], 1);
        g_esrc[pos] = s;
        g_ecoef[pos] = g_dinv[s] * g_dinv[d];
    }
}

// ---------------- input projection: h = relu(x @ W_in + b_in) ----------------
__global__ void k_inproj(const float* __restrict__ x,
                         const float* __restrict__ Win,
                         const float* __restrict__ bin) {
    __shared__ float xs[8];
    int i = blockIdx.x;
    int t = threadIdx.x;  // 0..127
    if (t < FF) xs[t] = x[i * FF + t];
    __syncthreads();
    float acc = bin[t];
#pragma unroll
    for (int k = 0; k < FF; k++) acc = fmaf(xs[k], Win[k * HH + t], acc);
    g_A[i * HH + t] = fmaxf(acc, 0.0f);
}

// ---------------- tiled SGEMM: g_B[N,DO] = g_A[N,128] @ W[128,DO] ----------------
template <int DO>
__global__ void k_sgemm(const float* __restrict__ W) {
    const int BM = 64, BK = 16;
    const int TM = 4, TN = DO / 16;  // 8 for DO=128, 4 for DO=64
    __shared__ float sA[BM][BK];
    __shared__ float sW[BK][DO];

    const float* __restrict__ A = g_A;
    float* __restrict__ C = g_B;

    int tid = threadIdx.x;            // 256 threads
    int tx = tid & 15, ty = tid >> 4; // 16 x 16 thread grid
    int rowBase = blockIdx.x * BM;

    float acc[TM][TN];
#pragma unroll
    for (int i = 0; i < TM; i++)
#pragma unroll
        for (int j = 0; j < TN; j++) acc[i][j] = 0.0f;

    for (int k0 = 0; k0 < HH; k0 += BK) {
        // A tile: 64 x 16 = 256 float4 loads, one per thread
        {
            int r = tid >> 2, c4 = tid & 3;
            int grow = rowBase + r;
            float4 v = make_float4(0.f, 0.f, 0.f, 0.f);
            if (grow < NN) v = *(const float4*)(A + grow * HH + k0 + c4 * 4);
            *(float4*)(&sA[r][c4 * 4]) = v;
        }
        // W tile: 16 x DO
        {
            const int nv = (BK * DO) / 4;
            for (int idx = tid; idx < nv; idx += 256) {
                int r = idx / (DO / 4);
                int c4 = idx % (DO / 4);
                *(float4*)(&sW[r][c4 * 4]) = *(const float4*)(W + (k0 + r) * DO + c4 * 4);
            }
        }
        __syncthreads();
#pragma unroll
        for (int kk = 0; kk < BK; kk++) {
            float a[TM];
#pragma unroll
            for (int i = 0; i < TM; i++) a[i] = sA[ty * TM + i][kk];
            float b[TN];
#pragma unroll
            for (int j = 0; j < TN; j += 4) {
                float4 bv = *(const float4*)(&sW[kk][tx * TN + j]);
                b[j] = bv.x; b[j + 1] = bv.y; b[j + 2] = bv.z; b[j + 3] = bv.w;
            }
#pragma unroll
            for (int i = 0; i < TM; i++)
#pragma unroll
                for (int j = 0; j < TN; j++) acc[i][j] = fmaf(a[i], b[j], acc[i][j]);
        }
        __syncthreads();
    }
#pragma unroll
    for (int i = 0; i < TM; i++) {
        int grow = rowBase + ty * TM + i;
        if (grow < NN) {
#pragma unroll
            for (int j = 0; j < TN; j++) C[grow * DO + tx * TN + j] = acc[i][j];
        }
    }
}

// ---------------- aggregation + fused epilogue ----------------
// agg[i] = sum_{e: dst=i} g_B[src_e] * coef_e  +  g_B[i]*dinv[i]^2
// y = BN(agg + bias); layers 0/1: y = relu(y) + g_A[i] (in-place); layer 2: write out
template <int DO, bool FINAL>
__global__ void k_agg(const float* __restrict__ bias,
                      const float* __restrict__ gg,
                      const float* __restrict__ bb,
                      const float* __restrict__ mm,
                      const float* __restrict__ vv,
                      float* __restrict__ outp) {
    __shared__ int   ss[128];
    __shared__ float sc[128];
    const float* __restrict__ Bm = g_B;
    int i = blockIdx.x;
    int t = threadIdx.x;  // DO threads
    float di = g_dinv[i];
    float acc = Bm[i * DO + t] * di * di;  // self-loop term

    int beg = g_rowptr[i], end = g_rowptr[i + 1];
    for (int base = beg; base < end; base += 128) {
        int cnt = min(128, end - base);
        __syncthreads();
        for (int j = t; j < cnt; j += DO) {
            ss[j] = g_esrc[base + j];
            sc[j] = g_ecoef[base + j];
        }
        __syncthreads();
        for (int j = 0; j < cnt; j++)
            acc = fmaf(Bm[ss[j] * DO + t], sc[j], acc);
    }

    float scale = gg[t] * rsqrtf(vv[t] + EPSV);
    float y = (acc + bias[t] - mm[t]) * scale + bb[t];
    if (FINAL) {
        outp[i * DO + t] = y;
    } else {
        y = fmaxf(y, 0.0f) + g_A[i * DO + t];
        g_A[i * DO + t] = y;
    }
}

// ---------------- host ----------------
extern "C" void kernel_launch(void* const* d_in, const int* in_sizes, int n_in,
                              void* d_out, int out_size) {
    const float* x    = (const float*)d_in[0];
    const int*   ei   = (const int*)d_in[1];   // int32! (JAX x64 disabled)
    const float* W_in = (const float*)d_in[2];
    const float* b_in = (const float*)d_in[3];
    const float* W0 = (const float*)d_in[4],  *b0 = (const float*)d_in[5];
    const float* g0 = (const float*)d_in[6],  *be0 = (const float*)d_in[7];
    const float* m0 = (const float*)d_in[8],  *v0 = (const float*)d_in[9];
    const float* W1 = (const float*)d_in[10], *b1 = (const float*)d_in[11];
    const float* g1 = (const float*)d_in[12], *be1 = (const float*)d_in[13];
    const float* m1 = (const float*)d_in[14], *v1 = (const float*)d_in[15];
    const float* W2 = (const float*)d_in[16], *b2 = (const float*)d_in[17];
    const float* g2 = (const float*)d_in[18], *be2 = (const float*)d_in[19];
    const float* m2 = (const float*)d_in[20], *v2 = (const float*)d_in[21];
    float* out = (float*)d_out;

    // CSR build + degree normalization
    k_zero_cnt<<<256, 256>>>();
    k_hist<<<1024, 256>>>(ei);
    k_dinv<<<(NN + 255) / 256, 256>>>();
    k_scan_local<<<NBLK, SCAN_BS>>>();
    k_scan_blocks<<<1, 32>>>();
    k_scan_add<<<NBLK, SCAN_BS>>>();
    k_scatter<<<1024, 256>>>(ei);

    // input projection
    k_inproj<<<NN, HH>>>(x, W_in, b_in);

    const int GB = (NN + 63) / 64;
    // layer 0
    k_sgemm<HH><<<GB, 256>>>(W0);
    k_agg<HH, false><<<NN, HH>>>(b0, g0, be0, m0, v0, nullptr);
    // layer 1
    k_sgemm<HH><<<GB, 256>>>(W1);
    k_agg<HH, false><<<NN, HH>>>(b1, g1, be1, m1, v1, nullptr);
    // layer 2 (final)
    k_sgemm<DD><<<GB, 256>>>(W2);
    k_agg<DD, true><<<NN, DD>>>(b2, g2, be2, m2, v2, out);
}

// round 6
// speedup vs baseline: 1.3039x; 1.3039x over previous
#include <cuda_runtime.h>
#include <cuda_fp16.h>

// Problem constants (fixed by the dataset)
#define NN   100000
#define EE   3200000
#define FF   7
#define HH   128
#define DD   64
#define EPSV 1e-5f

#define SCAN_BS 1024
#define NBLK ((NN + SCAN_BS - 1) / SCAN_BS)

// ---------------- device scratch (static; no allocations) ----------------
__device__ float  g_A[NN * HH];     // node features fp32 (h / h0 / h1, in-place residual)
__device__ __half g_Bh[NN * HH];    // per-layer X@W scratch in fp16 (gather operand)
__device__ float  g_dinv[NN];
__device__ int    g_cnt[NN];
__device__ int    g_rowptr[NN + 1];
__device__ int    g_fill[NN];
__device__ int    g_esrc[EE];
__device__ float  g_ecoef[EE];
__device__ int    g_blksums[NBLK];

// ---------------- CSR build ----------------
__global__ void k_zero_cnt() {
    for (int i = blockIdx.x * blockDim.x + threadIdx.x; i < NN; i += gridDim.x * blockDim.x)
        g_cnt[i] = 0;
}

// edge_index is int32 (JAX x64 disabled: jnp.int64 request silently yields int32)
__global__ void k_hist(const int* __restrict__ ei) {
    for (int e = blockIdx.x * blockDim.x + threadIdx.x; e < EE; e += gridDim.x * blockDim.x) {
        int d = ei[EE + e];
        atomicAdd(&g_cnt[d], 1);
    }
}

__global__ void k_dinv() {
    int i = blockIdx.x * blockDim.x + threadIdx.x;
    if (i < NN) g_dinv[i] = rsqrtf((float)g_cnt[i] + 1.0f);
}

__global__ void k_scan_local() {
    __shared__ int sh[SCAN_BS];
    int tid = threadIdx.x;
    int i = blockIdx.x * SCAN_BS + tid;
    int v = (i < NN) ? g_cnt[i] : 0;
    sh[tid] = v;
    __syncthreads();
    for (int off = 1; off < SCAN_BS; off <<= 1) {
        int t = (tid >= off) ? sh[tid - off] : 0;
        __syncthreads();
        sh[tid] += t;
        __syncthreads();
    }
    if (i < NN) g_rowptr[i] = sh[tid] - v;  // exclusive prefix within block
    if (tid == SCAN_BS - 1) g_blksums[blockIdx.x] = sh[tid];
}

__global__ void k_scan_blocks() {
    if (threadIdx.x == 0 && blockIdx.x == 0) {
        int run = 0;
        for (int b = 0; b < NBLK; b++) {
            int t = g_blksums[b];
            g_blksums[b] = run;
            run += t;
        }
    }
}

__global__ void k_scan_add() {
    int i = blockIdx.x * SCAN_BS + threadIdx.x;
    if (i < NN) {
        int r = g_rowptr[i] + g_blksums[blockIdx.x];
        g_rowptr[i] = r;
        g_fill[i] = r;
    }
    if (i == 0) g_rowptr[NN] = EE;
}

__global__ void k_scatter(const int* __restrict__ ei) {
    for (int e = blockIdx.x * blockDim.x + threadIdx.x; e < EE; e += gridDim.x * blockDim.x) {
        int s = ei[e];
        int d = ei[EE + e];
        int pos = atomicAdd(&g_fill[d], 1);
        g_esrc[pos] = s;
        g_ecoef[pos] = g_dinv[s] * g_dinv[d];
    }
}

// ---------------- input projection: h = relu(x @ W_in + b_in) ----------------
__global__ void k_inproj(const float* __restrict__ x,
                         const float* __restrict__ Win,
                         const float* __restrict__ bin) {
    __shared__ float xs[8];
    int i = blockIdx.x;
    int t = threadIdx.x;  // 0..127
    if (t < FF) xs[t] = x[i * FF + t];
    __syncthreads();
    float acc = bin[t];
#pragma unroll
    for (int k = 0; k < FF; k++) acc = fmaf(xs[k], Win[k * HH + t], acc);
    g_A[i * HH + t] = fmaxf(acc, 0.0f);
}

// ---------------- tiled SGEMM: g_Bh[N,DO] = half(g_A[N,128] @ W[128,DO]) ----------------
template <int DO>
__global__ void k_sgemm(const float* __restrict__ W) {
    const int BM = 64, BK = 16;
    const int TM = 4, TN = DO / 16;  // 8 for DO=128, 4 for DO=64
    __shared__ float sA[BM][BK];
    __shared__ float sW[BK][DO];

    const float* __restrict__ A = g_A;

    int tid = threadIdx.x;            // 256 threads
    int tx = tid & 15, ty = tid >> 4; // 16 x 16 thread grid
    int rowBase = blockIdx.x * BM;

    float acc[TM][TN];
#pragma unroll
    for (int i = 0; i < TM; i++)
#pragma unroll
        for (int j = 0; j < TN; j++) acc[i][j] = 0.0f;

    for (int k0 = 0; k0 < HH; k0 += BK) {
        // A tile: 64 x 16 = 256 float4 loads, one per thread
        {
            int r = tid >> 2, c4 = tid & 3;
            int grow = rowBase + r;
            float4 v = make_float4(0.f, 0.f, 0.f, 0.f);
            if (grow < NN) v = *(const float4*)(A + grow * HH + k0 + c4 * 4);
            *(float4*)(&sA[r][c4 * 4]) = v;
        }
        // W tile: 16 x DO
        {
            const int nv = (BK * DO) / 4;
            for (int idx = tid; idx < nv; idx += 256) {
                int r = idx / (DO / 4);
                int c4 = idx % (DO / 4);
                *(float4*)(&sW[r][c4 * 4]) = *(const float4*)(W + (k0 + r) * DO + c4 * 4);
            }
        }
        __syncthreads();
#pragma unroll
        for (int kk = 0; kk < BK; kk++) {
            float a[TM];
#pragma unroll
            for (int i = 0; i < TM; i++) a[i] = sA[ty * TM + i][kk];
            float b[TN];
#pragma unroll
            for (int j = 0; j < TN; j += 4) {
                float4 bv = *(const float4*)(&sW[kk][tx * TN + j]);
                b[j] = bv.x; b[j + 1] = bv.y; b[j + 2] = bv.z; b[j + 3] = bv.w;
            }
#pragma unroll
            for (int i = 0; i < TM; i++)
#pragma unroll
                for (int j = 0; j < TN; j++) acc[i][j] = fmaf(a[i], b[j], acc[i][j]);
        }
        __syncthreads();
    }
    __half2* Ch = (__half2*)g_Bh;
#pragma unroll
    for (int i = 0; i < TM; i++) {
        int grow = rowBase + ty * TM + i;
        if (grow < NN) {
#pragma unroll
            for (int j = 0; j < TN; j += 2) {
                __half2 hv = __floats2half2_rn(acc[i][j], acc[i][j + 1]);
                Ch[(grow * DO + tx * TN + j) >> 1] = hv;
            }
        }
    }
}

// ---------------- aggregation + fused epilogue (fp16 gather, fp32 accumulate) ----------------
// agg[i] = sum_{e: dst=i} g_Bh[src_e] * coef_e  +  g_Bh[i]*dinv[i]^2
// y = BN(agg + bias); layers 0/1: y = relu(y) + g_A[i] (in-place); layer 2: write out
template <int DO, bool FINAL>
__global__ void k_agg(const float* __restrict__ bias,
                      const float* __restrict__ gg,
                      const float* __restrict__ bb,
                      const float* __restrict__ mm,
                      const float* __restrict__ vv,
                      float* __restrict__ outp) {
    const int NT = DO / 2;  // threads per block; each owns 2 channels via half2
    __shared__ int   ss[64];
    __shared__ float sc[64];
    const __half2* __restrict__ Bm = (const __half2*)g_Bh;
    int i = blockIdx.x;
    int t = threadIdx.x;  // 0..NT-1
    float di = g_dinv[i];
    float dii = di * di;
    float2 sf = __half22float2(Bm[i * NT + t]);
    float accx = sf.x * dii, accy = sf.y * dii;  // self-loop term

    int beg = g_rowptr[i], end = g_rowptr[i + 1];
    for (int base = beg; base < end; base += 64) {
        int cnt = min(64, end - base);
        __syncthreads();
        for (int j = t; j < cnt; j += NT) {
            ss[j] = g_esrc[base + j] * NT;  // pre-scaled row base (half2 units)
            sc[j] = g_ecoef[base + j];
        }
        __syncthreads();
        int j = 0;
        for (; j + 4 <= cnt; j += 4) {
            float2 a0 = __half22float2(Bm[ss[j] + t]);
            float2 a1 = __half22float2(Bm[ss[j + 1] + t]);
            float2 a2 = __half22float2(Bm[ss[j + 2] + t]);
            float2 a3 = __half22float2(Bm[ss[j + 3] + t]);
            accx = fmaf(a0.x, sc[j], accx);     accy = fmaf(a0.y, sc[j], accy);
            accx = fmaf(a1.x, sc[j + 1], accx); accy = fmaf(a1.y, sc[j + 1], accy);
            accx = fmaf(a2.x, sc[j + 2], accx); accy = fmaf(a2.y, sc[j + 2], accy);
            accx = fmaf(a3.x, sc[j + 3], accx); accy = fmaf(a3.y, sc[j + 3], accy);
        }
        for (; j < cnt; j++) {
            float2 a = __half22float2(Bm[ss[j] + t]);
            accx = fmaf(a.x, sc[j], accx);
            accy = fmaf(a.y, sc[j], accy);
        }
    }

    int c0 = 2 * t, c1 = 2 * t + 1;
    float s0 = gg[c0] * rsqrtf(vv[c0] + EPSV);
    float s1 = gg[c1] * rsqrtf(vv[c1] + EPSV);
    float y0 = (accx + bias[c0] - mm[c0]) * s0 + bb[c0];
    float y1 = (accy + bias[c1] - mm[c1]) * s1 + bb[c1];
    if (FINAL) {
        ((float2*)outp)[i * NT + t] = make_float2(y0, y1);
    } else {
        float2* Ares = (float2*)g_A;
        float2 r = Ares[i * NT + t];
        r.x += fmaxf(y0, 0.0f);
        r.y += fmaxf(y1, 0.0f);
        Ares[i * NT + t] = r;
    }
}

// ---------------- host ----------------
extern "C" void kernel_launch(void* const* d_in, const int* in_sizes, int n_in,
                              void* d_out, int out_size) {
    const float* x    = (const float*)d_in[0];
    const int*   ei   = (const int*)d_in[1];   // int32! (JAX x64 disabled)
    const float* W_in = (const float*)d_in[2];
    const float* b_in = (const float*)d_in[3];
    const float* W0 = (const float*)d_in[4],  *b0 = (const float*)d_in[5];
    const float* g0 = (const float*)d_in[6],  *be0 = (const float*)d_in[7];
    const float* m0 = (const float*)d_in[8],  *v0 = (const float*)d_in[9];
    const float* W1 = (const float*)d_in[10], *b1 = (const float*)d_in[11];
    const float* g1 = (const float*)d_in[12], *be1 = (const float*)d_in[13];
    const float* m1 = (const float*)d_in[14], *v1 = (const float*)d_in[15];
    const float* W2 = (const float*)d_in[16], *b2 = (const float*)d_in[17];
    const float* g2 = (const float*)d_in[18], *be2 = (const float*)d_in[19];
    const float* m2 = (const float*)d_in[20], *v2 = (const float*)d_in[21];
    float* out = (float*)d_out;

    // CSR build + degree normalization
    k_zero_cnt<<<256, 256>>>();
    k_hist<<<1024, 256>>>(ei);
    k_dinv<<<(NN + 255) / 256, 256>>>();
    k_scan_local<<<NBLK, SCAN_BS>>>();
    k_scan_blocks<<<1, 32>>>();
    k_scan_add<<<NBLK, SCAN_BS>>>();
    k_scatter<<<1024, 256>>>(ei);

    // input projection
    k_inproj<<<NN, HH>>>(x, W_in, b_in);

    const int GB = (NN + 63) / 64;
    // layer 0
    k_sgemm<HH><<<GB, 256>>>(W0);
    k_agg<HH, false><<<NN, HH / 2>>>(b0, g0, be0, m0, v0, nullptr);
    // layer 1
    k_sgemm<HH><<<GB, 256>>>(W1);
    k_agg<HH, false><<<NN, HH / 2>>>(b1, g1, be1, m1, v1, nullptr);
    // layer 2 (final)
    k_sgemm<DD><<<GB, 256>>>(W2);
    k_agg<DD, true><<<NN, DD / 2>>>(b2, g2, be2, m2, v2, out);
}

// round 8
// speedup vs baseline: 1.6855x; 1.2927x over previous
#include <cuda_runtime.h>
#include <cuda_fp16.h>
#include <cstdint>

// Problem constants (fixed by the dataset)
#define NN   100000
#define EE   3200000
#define FF   7
#define HH   128
#define DD   64
#define EPSV 1e-5f

#define SCAN_BS 1024
#define NBLK ((NN + SCAN_BS - 1) / SCAN_BS)

// ---------------- device scratch (static; no allocations) ----------------
__device__ float  g_A[NN * HH];     // node features fp32 (h / h0 / h1, in-place residual)
__device__ __half g_Bh[NN * HH];    // per-layer X@W scratch in fp16 (gather operand)
__device__ float  g_dinv[NN];
__device__ int    g_cnt[NN];
__device__ int    g_rowptr[NN + 1];
__device__ int    g_fill[NN];
__device__ int    g_esrc[EE];
__device__ float  g_ecoef[EE];
__device__ int    g_blksums[NBLK];

// ---------------- CSR build ----------------
__global__ void k_zero_cnt() {
    for (int i = blockIdx.x * blockDim.x + threadIdx.x; i < NN; i += gridDim.x * blockDim.x)
        g_cnt[i] = 0;
}

// edge_index is int32 (JAX x64 disabled: jnp.int64 request silently yields int32)
__global__ void k_hist(const int* __restrict__ ei) {
    for (int e = blockIdx.x * blockDim.x + threadIdx.x; e < EE; e += gridDim.x * blockDim.x) {
        int d = ei[EE + e];
        atomicAdd(&g_cnt[d], 1);
    }
}

__global__ void k_dinv() {
    int i = blockIdx.x * blockDim.x + threadIdx.x;
    if (i < NN) g_dinv[i] = rsqrtf((float)g_cnt[i] + 1.0f);
}

__global__ void k_scan_local() {
    __shared__ int sh[SCAN_BS];
    int tid = threadIdx.x;
    int i = blockIdx.x * SCAN_BS + tid;
    int v = (i < NN) ? g_cnt[i] : 0;
    sh[tid] = v;
    __syncthreads();
    for (int off = 1; off < SCAN_BS; off <<= 1) {
        int t = (tid >= off) ? sh[tid - off] : 0;
        __syncthreads();
        sh[tid] += t;
        __syncthreads();
    }
    if (i < NN) g_rowptr[i] = sh[tid] - v;  // exclusive prefix within block
    if (tid == SCAN_BS - 1) g_blksums[blockIdx.x] = sh[tid];
}

__global__ void k_scan_blocks() {
    if (threadIdx.x == 0 && blockIdx.x == 0) {
        int run = 0;
        for (int b = 0; b < NBLK; b++) {
            int t = g_blksums[b];
            g_blksums[b] = run;
            run += t;
        }
    }
}

__global__ void k_scan_add() {
    int i = blockIdx.x * SCAN_BS + threadIdx.x;
    if (i < NN) {
        int r = g_rowptr[i] + g_blksums[blockIdx.x];
        g_rowptr[i] = r;
        g_fill[i] = r;
    }
    if (i == 0) g_rowptr[NN] = EE;
}

__global__ void k_scatter(const int* __restrict__ ei) {
    for (int e = blockIdx.x * blockDim.x + threadIdx.x; e < EE; e += gridDim.x * blockDim.x) {
        int s = ei[e];
        int d = ei[EE + e];
        int pos = atomicAdd(&g_fill[d], 1);
        g_esrc[pos] = s;
        g_ecoef[pos] = g_dinv[s] * g_dinv[d];
    }
}

// ---------------- input projection: h = relu(x @ W_in + b_in) ----------------
__global__ void k_inproj(const float* __restrict__ x,
                         const float* __restrict__ Win,
                         const float* __restrict__ bin) {
    __shared__ float xs[8];
    int i = blockIdx.x;
    int t = threadIdx.x;  // 0..127
    if (t < FF) xs[t] = x[i * FF + t];
    __syncthreads();
    float acc = bin[t];
#pragma unroll
    for (int k = 0; k < FF; k++) acc = fmaf(xs[k], Win[k * HH + t], acc);
    g_A[i * HH + t] = fmaxf(acc, 0.0f);
}

// ---------------- helpers for tensor-core GEMM ----------------
__device__ __forceinline__ uint32_t s2u(const void* p) {
    return (uint32_t)__cvta_generic_to_shared(p);
}
__device__ __forceinline__ void ldsm_x4(uint32_t& r0, uint32_t& r1, uint32_t& r2, uint32_t& r3,
                                        uint32_t addr) {
    asm volatile("ldmatrix.sync.aligned.m8n8.x4.shared.b16 {%0,%1,%2,%3}, [%4];"
                 : "=r"(r0), "=r"(r1), "=r"(r2), "=r"(r3) : "r"(addr));
}
__device__ __forceinline__ void ldsm_x2t(uint32_t& r0, uint32_t& r1, uint32_t addr) {
    asm volatile("ldmatrix.sync.aligned.m8n8.x2.trans.shared.b16 {%0,%1}, [%2];"
                 : "=r"(r0), "=r"(r1) : "r"(addr));
}
__device__ __forceinline__ void mma16816(float* d, const uint32_t* a, const uint32_t* b) {
    asm volatile(
        "mma.sync.aligned.m16n8k16.row.col.f32.f16.f16.f32 "
        "{%0,%1,%2,%3}, {%4,%5,%6,%7}, {%8,%9}, {%0,%1,%2,%3};"
        : "+f"(d[0]), "+f"(d[1]), "+f"(d[2]), "+f"(d[3])
        : "r"(a[0]), "r"(a[1]), "r"(a[2]), "r"(a[3]), "r"(b[0]), "r"(b[1]));
}

// ---------------- fp16 tensor-core GEMM: g_Bh[N,DO] = half(g_A[N,128] @ W[128,DO]) ----
// BM=128 rows/block, full K=128 resident in smem, 8 warps (4 m-tiles x 2 n-tiles).
template <int DO>
__global__ void k_hgemm(const float* __restrict__ W) {
    const int SAP = HH + 8;   // padded row stride (halves): conflict-free ldmatrix
    const int SWP = DO + 8;
    extern __shared__ __half sm[];
    __half* sA = sm;                 // [128][SAP]
    __half* sW = sm + 128 * SAP;     // [128][SWP]

    int tid = threadIdx.x;           // 256
    int wid = tid >> 5, lane = tid & 31;
    int rowBase = blockIdx.x * 128;

    // load A tile (128 x 128 fp32 -> fp16), 2 threads per row
    {
        int r = tid >> 1;
        int cbase = (tid & 1) * 64;
        const float* Arow = g_A + (size_t)(rowBase + r) * HH + cbase;
        bool valid = (rowBase + r) < NN;
        __half* dst = sA + r * SAP + cbase;
#pragma unroll
        for (int i = 0; i < 16; i++) {
            float4 v = valid ? *(const float4*)(Arow + i * 4) : make_float4(0.f, 0.f, 0.f, 0.f);
            *(__half2*)(dst + i * 4)     = __floats2half2_rn(v.x, v.y);
            *(__half2*)(dst + i * 4 + 2) = __floats2half2_rn(v.z, v.w);
        }
    }
    // load W (128 x DO fp32 -> fp16), 2 threads per row
    {
        const int CPT = DO / 2;
        int r = tid >> 1;
        int cbase = (tid & 1) * CPT;
        const float* Wrow = W + r * DO + cbase;
        __half* dst = sW + r * SWP + cbase;
#pragma unroll
        for (int i = 0; i < CPT / 4; i++) {
            float4 v = *(const float4*)(Wrow + i * 4);
            *(__half2*)(dst + i * 4)     = __floats2half2_rn(v.x, v.y);
            *(__half2*)(dst + i * 4 + 2) = __floats2half2_rn(v.z, v.w);
        }
    }
    __syncthreads();

    const int NT = DO / 16;          // n8 tiles per warp (8 for DO=128, 4 for DO=64)
    int warp_m = wid & 3, warp_n = wid >> 2;
    int m0 = warp_m * 32, n0 = warp_n * (DO / 2);

    float acc[2][NT][4];
#pragma unroll
    for (int mt = 0; mt < 2; mt++)
#pragma unroll
        for (int nt = 0; nt < NT; nt++)
#pragma unroll
            for (int q = 0; q < 4; q++) acc[mt][nt][q] = 0.0f;

    int lr = lane & 15;              // row-within-16 selector
    int lc = (lane >> 4) * 8;        // col half selector (A frags)

#pragma unroll
    for (int k = 0; k < HH; k += 16) {
        uint32_t a[2][4];
#pragma unroll
        for (int mt = 0; mt < 2; mt++) {
            uint32_t addr = s2u(sA + (m0 + mt * 16 + lr) * SAP + k + lc);
            ldsm_x4(a[mt][0], a[mt][1], a[mt][2], a[mt][3], addr);
        }
        uint32_t b[NT][2];
#pragma unroll
        for (int nt = 0; nt < NT; nt++) {
            uint32_t addr = s2u(sW + (k + lr) * SWP + n0 + nt * 8);
            ldsm_x2t(b[nt][0], b[nt][1], addr);
        }
#pragma unroll
        for (int mt = 0; mt < 2; mt++)
#pragma unroll
            for (int nt = 0; nt < NT; nt++)
                mma16816(acc[mt][nt], a[mt], b[nt]);
    }

    // epilogue: fp32 acc -> half2 stores into g_Bh
    __half2* Ch = (__half2*)g_Bh;
    int rq = lane >> 2;              // 0..7
    int cq = (lane & 3) * 2;
#pragma unroll
    for (int mt = 0; mt < 2; mt++) {
#pragma unroll
        for (int nt = 0; nt < NT; nt++) {
            int col = n0 + nt * 8 + cq;
            int row0 = rowBase + m0 + mt * 16 + rq;
            int row1 = row0 + 8;
            if (row0 < NN)
                Ch[(row0 * DO + col) >> 1] = __floats2half2_rn(acc[mt][nt][0], acc[mt][nt][1]);
            if (row1 < NN)
                Ch[(row1 * DO + col) >> 1] = __floats2half2_rn(acc[mt][nt][2], acc[mt][nt][3]);
        }
    }
}

// ---------------- aggregation + fused epilogue (fp16 gather, fp32 accumulate) ----------------
template <int DO, bool FINAL>
__global__ void k_agg(const float* __restrict__ bias,
                      const float* __restrict__ gg,
                      const float* __restrict__ bb,
                      const float* __restrict__ mm,
                      const float* __restrict__ vv,
                      float* __restrict__ outp) {
    const int NT = DO / 2;  // threads per block; each owns 2 channels via half2
    __shared__ int   ss[64];
    __shared__ float sc[64];
    const __half2* __restrict__ Bm = (const __half2*)g_Bh;
    int i = blockIdx.x;
    int t = threadIdx.x;  // 0..NT-1
    float di = g_dinv[i];
    float dii = di * di;
    float2 sf = __half22float2(Bm[i * NT + t]);
    float accx = sf.x * dii, accy = sf.y * dii;  // self-loop term

    int beg = g_rowptr[i], end = g_rowptr[i + 1];
    for (int base = beg; base < end; base += 64) {
        int cnt = min(64, end - base);
        __syncthreads();
        for (int j = t; j < cnt; j += NT) {
            ss[j] = g_esrc[base + j] * NT;  // pre-scaled row base (half2 units)
            sc[j] = g_ecoef[base + j];
        }
        __syncthreads();
        int j = 0;
        for (; j + 4 <= cnt; j += 4) {
            float2 a0 = __half22float2(Bm[ss[j] + t]);
            float2 a1 = __half22float2(Bm[ss[j + 1] + t]);
            float2 a2 = __half22float2(Bm[ss[j + 2] + t]);
            float2 a3 = __half22float2(Bm[ss[j + 3] + t]);
            accx = fmaf(a0.x, sc[j], accx);     accy = fmaf(a0.y, sc[j], accy);
            accx = fmaf(a1.x, sc[j + 1], accx); accy = fmaf(a1.y, sc[j + 1], accy);
            accx = fmaf(a2.x, sc[j + 2], accx); accy = fmaf(a2.y, sc[j + 2], accy);
            accx = fmaf(a3.x, sc[j + 3], accx); accy = fmaf(a3.y, sc[j + 3], accy);
        }
        for (; j < cnt; j++) {
            float2 a = __half22float2(Bm[ss[j] + t]);
            accx = fmaf(a.x, sc[j], accx);
            accy = fmaf(a.y, sc[j], accy);
        }
    }

    int c0 = 2 * t, c1 = 2 * t + 1;
    float s0 = gg[c0] * rsqrtf(vv[c0] + EPSV);
    float s1 = gg[c1] * rsqrtf(vv[c1] + EPSV);
    float y0 = (accx + bias[c0] - mm[c0]) * s0 + bb[c0];
    float y1 = (accy + bias[c1] - mm[c1]) * s1 + bb[c1];
    if (FINAL) {
        ((float2*)outp)[i * NT + t] = make_float2(y0, y1);
    } else {
        float2* Ares = (float2*)g_A;
        float2 r = Ares[i * NT + t];
        r.x += fmaxf(y0, 0.0f);
        r.y += fmaxf(y1, 0.0f);
        Ares[i * NT + t] = r;
    }
}

// ---------------- host ----------------
extern "C" void kernel_launch(void* const* d_in, const int* in_sizes, int n_in,
                              void* d_out, int out_size) {
    const float* x    = (const float*)d_in[0];
    const int*   ei   = (const int*)d_in[1];   // int32! (JAX x64 disabled)
    const float* W_in = (const float*)d_in[2];
    const float* b_in = (const float*)d_in[3];
    const float* W0 = (const float*)d_in[4],  *b0 = (const float*)d_in[5];
    const float* g0 = (const float*)d_in[6],  *be0 = (const float*)d_in[7];
    const float* m0 = (const float*)d_in[8],  *v0 = (const float*)d_in[9];
    const float* W1 = (const float*)d_in[10], *b1 = (const float*)d_in[11];
    const float* g1 = (const float*)d_in[12], *be1 = (const float*)d_in[13];
    const float* m1 = (const float*)d_in[14], *v1 = (const float*)d_in[15];
    const float* W2 = (const float*)d_in[16], *b2 = (const float*)d_in[17];
    const float* g2 = (const float*)d_in[18], *be2 = (const float*)d_in[19];
    const float* m2 = (const float*)d_in[20], *v2 = (const float*)d_in[21];
    float* out = (float*)d_out;

    // dynamic smem sizes for the fp16 GEMMs (exceed 48KB static limit)
    const int SMEM_H = 128 * (HH + 8 + HH + 8) * (int)sizeof(__half);   // DO=128
    const int SMEM_D = 128 * (HH + 8 + DD + 8) * (int)sizeof(__half);   // DO=64
    cudaFuncSetAttribute(k_hgemm<HH>, cudaFuncAttributeMaxDynamicSharedMemorySize, SMEM_H);
    cudaFuncSetAttribute(k_hgemm<DD>, cudaFuncAttributeMaxDynamicSharedMemorySize, SMEM_D);

    // CSR build + degree normalization
    k_zero_cnt<<<256, 256>>>();
    k_hist<<<1024, 256>>>(ei);
    k_dinv<<<(NN + 255) / 256, 256>>>();
    k_scan_local<<<NBLK, SCAN_BS>>>();
    k_scan_blocks<<<1, 32>>>();
    k_scan_add<<<NBLK, SCAN_BS>>>();
    k_scatter<<<1024, 256>>>(ei);

    // input projection
    k_inproj<<<NN, HH>>>(x, W_in, b_in);

    const int GB = (NN + 127) / 128;
    // layer 0
    k_hgemm<HH><<<GB, 256, SMEM_H>>>(W0);
    k_agg<HH, false><<<NN, HH / 2>>>(b0, g0, be0, m0, v0, nullptr);
    // layer 1
    k_hgemm<HH><<<GB, 256, SMEM_H>>>(W1);
    k_agg<HH, false><<<NN, HH / 2>>>(b1, g1, be1, m1, v1, nullptr);
    // layer 2 (final)
    k_hgemm<DD><<<GB, 256, SMEM_D>>>(W2);
    k_agg<DD, true><<<NN, DD / 2>>>(b2, g2, be2, m2, v2, out);
}

// round 10
// speedup vs baseline: 1.7539x; 1.0406x over previous
#include <cuda_runtime.h>
#include <cuda_fp16.h>
#include <cstdint>

// Problem constants (fixed by the dataset)
#define NN   100000
#define EE   3200000
#define FF   7
#define HH   128
#define DD   64
#define EPSV 1e-5f

#define SCAN_BS 1024
#define NBLK ((NN + SCAN_BS - 1) / SCAN_BS)

// ---------------- device scratch (static; no allocations) ----------------
__device__ float  g_A[NN * HH];     // node features fp32 (h / h0 / h1, in-place residual)
__device__ __half g_Bh[NN * HH];    // per-layer X@W scratch in fp16 (gather operand)
__device__ float  g_dinv[NN];
__device__ int    g_cnt[NN];
__device__ int    g_rowptr[NN + 1];
__device__ int    g_fill[NN];
__device__ int2   g_edge[EE];       // packed {src, coef-bits}
__device__ int    g_blksums[NBLK];

// ---------------- CSR build ----------------
__global__ void k_zero_cnt() {
    for (int i = blockIdx.x * blockDim.x + threadIdx.x; i < NN; i += gridDim.x * blockDim.x)
        g_cnt[i] = 0;
}

// edge_index is int32 (JAX x64 disabled: jnp.int64 request silently yields int32)
__global__ void k_hist(const int* __restrict__ ei) {
    for (int e = blockIdx.x * blockDim.x + threadIdx.x; e < EE; e += gridDim.x * blockDim.x) {
        int d = ei[EE + e];
        atomicAdd(&g_cnt[d], 1);
    }
}

__global__ void k_scan_local() {
    __shared__ int sh[SCAN_BS];
    int tid = threadIdx.x;
    int i = blockIdx.x * SCAN_BS + tid;
    int v = (i < NN) ? g_cnt[i] : 0;
    if (i < NN) g_dinv[i] = rsqrtf((float)v + 1.0f);   // fused dinv
    sh[tid] = v;
    __syncthreads();
    for (int off = 1; off < SCAN_BS; off <<= 1) {
        int t = (tid >= off) ? sh[tid - off] : 0;
        __syncthreads();
        sh[tid] += t;
        __syncthreads();
    }
    if (i < NN) g_rowptr[i] = sh[tid] - v;  // exclusive prefix within block
    if (tid == SCAN_BS - 1) g_blksums[blockIdx.x] = sh[tid];
}

__global__ void k_scan_blocks() {
    if (threadIdx.x == 0 && blockIdx.x == 0) {
        int run = 0;
        for (int b = 0; b < NBLK; b++) {
            int t = g_blksums[b];
            g_blksums[b] = run;
            run += t;
        }
    }
}

__global__ void k_scan_add() {
    int i = blockIdx.x * SCAN_BS + threadIdx.x;
    if (i < NN) {
        int r = g_rowptr[i] + g_blksums[blockIdx.x];
        g_rowptr[i] = r;
        g_fill[i] = r;
    }
    if (i == 0) g_rowptr[NN] = EE;
}

__global__ void k_scatter(const int* __restrict__ ei) {
    for (int e = blockIdx.x * blockDim.x + threadIdx.x; e < EE; e += gridDim.x * blockDim.x) {
        int s = ei[e];
        int d = ei[EE + e];
        int pos = atomicAdd(&g_fill[d], 1);
        float coef = g_dinv[s] * g_dinv[d];
        g_edge[pos] = make_int2(s, __float_as_int(coef));
    }
}

// ---------------- input projection: h = relu(x @ W_in + b_in) ----------------
__global__ void k_inproj(const float* __restrict__ x,
                         const float* __restrict__ Win,
                         const float* __restrict__ bin) {
    __shared__ float xs[8];
    int i = blockIdx.x;
    int t = threadIdx.x;  // 0..127
    if (t < FF) xs[t] = x[i * FF + t];
    __syncthreads();
    float acc = bin[t];
#pragma unroll
    for (int k = 0; k < FF; k++) acc = fmaf(xs[k], Win[k * HH + t], acc);
    g_A[i * HH + t] = fmaxf(acc, 0.0f);
}

// ---------------- helpers for tensor-core GEMM ----------------
__device__ __forceinline__ uint32_t s2u(const void* p) {
    return (uint32_t)__cvta_generic_to_shared(p);
}
__device__ __forceinline__ void ldsm_x4(uint32_t& r0, uint32_t& r1, uint32_t& r2, uint32_t& r3,
                                        uint32_t addr) {
    asm volatile("ldmatrix.sync.aligned.m8n8.x4.shared.b16 {%0,%1,%2,%3}, [%4];"
                 : "=r"(r0), "=r"(r1), "=r"(r2), "=r"(r3) : "r"(addr));
}
__device__ __forceinline__ void ldsm_x2t(uint32_t& r0, uint32_t& r1, uint32_t addr) {
    asm volatile("ldmatrix.sync.aligned.m8n8.x2.trans.shared.b16 {%0,%1}, [%2];"
                 : "=r"(r0), "=r"(r1) : "r"(addr));
}
__device__ __forceinline__ void mma16816(float* d, const uint32_t* a, const uint32_t* b) {
    asm volatile(
        "mma.sync.aligned.m16n8k16.row.col.f32.f16.f16.f32 "
        "{%0,%1,%2,%3}, {%4,%5,%6,%7}, {%8,%9}, {%0,%1,%2,%3};"
        : "+f"(d[0]), "+f"(d[1]), "+f"(d[2]), "+f"(d[3])
        : "r"(a[0]), "r"(a[1]), "r"(a[2]), "r"(a[3]), "r"(b[0]), "r"(b[1]));
}

// ---------------- fp16 tensor-core GEMM: g_Bh[N,DO] = half(g_A[N,128] @ W[128,DO]) ----
template <int DO>
__global__ void k_hgemm(const float* __restrict__ W) {
    const int SAP = HH + 8;
    const int SWP = DO + 8;
    extern __shared__ __half sm[];
    __half* sA = sm;                 // [128][SAP]
    __half* sW = sm + 128 * SAP;     // [128][SWP]

    int tid = threadIdx.x;           // 256
    int wid = tid >> 5, lane = tid & 31;
    int rowBase = blockIdx.x * 128;

    // load A tile (128 x 128 fp32 -> fp16), 2 threads per row
    {
        int r = tid >> 1;
        int cbase = (tid & 1) * 64;
        const float* Arow = g_A + (size_t)(rowBase + r) * HH + cbase;
        bool valid = (rowBase + r) < NN;
        __half* dst = sA + r * SAP + cbase;
#pragma unroll
        for (int i = 0; i < 16; i++) {
            float4 v = valid ? *(const float4*)(Arow + i * 4) : make_float4(0.f, 0.f, 0.f, 0.f);
            *(__half2*)(dst + i * 4)     = __floats2half2_rn(v.x, v.y);
            *(__half2*)(dst + i * 4 + 2) = __floats2half2_rn(v.z, v.w);
        }
    }
    // load W (128 x DO fp32 -> fp16), 2 threads per row
    {
        const int CPT = DO / 2;
        int r = tid >> 1;
        int cbase = (tid & 1) * CPT;
        const float* Wrow = W + r * DO + cbase;
        __half* dst = sW + r * SWP + cbase;
#pragma unroll
        for (int i = 0; i < CPT / 4; i++) {
            float4 v = *(const float4*)(Wrow + i * 4);
            *(__half2*)(dst + i * 4)     = __floats2half2_rn(v.x, v.y);
            *(__half2*)(dst + i * 4 + 2) = __floats2half2_rn(v.z, v.w);
        }
    }
    __syncthreads();

    const int NT = DO / 16;
    int warp_m = wid & 3, warp_n = wid >> 2;
    int m0 = warp_m * 32, n0 = warp_n * (DO / 2);

    float acc[2][NT][4];
#pragma unroll
    for (int mt = 0; mt < 2; mt++)
#pragma unroll
        for (int nt = 0; nt < NT; nt++)
#pragma unroll
            for (int q = 0; q < 4; q++) acc[mt][nt][q] = 0.0f;

    int lr = lane & 15;
    int lc = (lane >> 4) * 8;

#pragma unroll
    for (int k = 0; k < HH; k += 16) {
        uint32_t a[2][4];
#pragma unroll
        for (int mt = 0; mt < 2; mt++) {
            uint32_t addr = s2u(sA + (m0 + mt * 16 + lr) * SAP + k + lc);
            ldsm_x4(a[mt][0], a[mt][1], a[mt][2], a[mt][3], addr);
        }
        uint32_t b[NT][2];
#pragma unroll
        for (int nt = 0; nt < NT; nt++) {
            uint32_t addr = s2u(sW + (k + lr) * SWP + n0 + nt * 8);
            ldsm_x2t(b[nt][0], b[nt][1], addr);
        }
#pragma unroll
        for (int mt = 0; mt < 2; mt++)
#pragma unroll
            for (int nt = 0; nt < NT; nt++)
                mma16816(acc[mt][nt], a[mt], b[nt]);
    }

    __half2* Ch = (__half2*)g_Bh;
    int rq = lane >> 2;
    int cq = (lane & 3) * 2;
#pragma unroll
    for (int mt = 0; mt < 2; mt++) {
#pragma unroll
        for (int nt = 0; nt < NT; nt++) {
            int col = n0 + nt * 8 + cq;
            int row0 = rowBase + m0 + mt * 16 + rq;
            int row1 = row0 + 8;
            if (row0 < NN)
                Ch[(row0 * DO + col) >> 1] = __floats2half2_rn(acc[mt][nt][0], acc[mt][nt][1]);
            if (row1 < NN)
                Ch[(row1 * DO + col) >> 1] = __floats2half2_rn(acc[mt][nt][2], acc[mt][nt][3]);
        }
    }
}

// ---------------- aggregation + fused epilogue (fp16 gather, fp32 accumulate) ----------------
template <int DO, bool FINAL>
__global__ void k_agg(const float* __restrict__ bias,
                      const float* __restrict__ gg,
                      const float* __restrict__ bb,
                      const float* __restrict__ mm,
                      const float* __restrict__ vv,
                      float* __restrict__ outp) {
    const int NT = DO / 2;  // threads per block; each owns 2 channels via half2
    __shared__ int2 se[64];
    const __half2* __restrict__ Bm = (const __half2*)g_Bh;
    int i = blockIdx.x;
    int t = threadIdx.x;  // 0..NT-1
    float di = g_dinv[i];
    float dii = di * di;
    float2 sf = __half22float2(Bm[i * NT + t]);
    float accx = sf.x * dii, accy = sf.y * dii;  // self-loop term

    int beg = g_rowptr[i], end = g_rowptr[i + 1];
    for (int base = beg; base < end; base += 64) {
        int cnt = min(64, end - base);
        __syncthreads();
        for (int j = t; j < cnt; j += NT) {
            int2 e = g_edge[base + j];
            e.x *= NT;  // pre-scaled row base (half2 units)
            se[j] = e;
        }
        __syncthreads();
        int j = 0;
        for (; j + 4 <= cnt; j += 4) {
            int2 e0 = se[j], e1 = se[j + 1], e2 = se[j + 2], e3 = se[j + 3];
            float2 a0 = __half22float2(Bm[e0.x + t]);
            float2 a1 = __half22float2(Bm[e1.x + t]);
            float2 a2 = __half22float2(Bm[e2.x + t]);
            float2 a3 = __half22float2(Bm[e3.x + t]);
            float c0 = __int_as_float(e0.y), c1 = __int_as_float(e1.y);
            float c2 = __int_as_float(e2.y), c3 = __int_as_float(e3.y);
            accx = fmaf(a0.x, c0, accx); accy = fmaf(a0.y, c0, accy);
            accx = fmaf(a1.x, c1, accx); accy = fmaf(a1.y, c1, accy);
            accx = fmaf(a2.x, c2, accx); accy = fmaf(a2.y, c2, accy);
            accx = fmaf(a3.x, c3, accx); accy = fmaf(a3.y, c3, accy);
        }
        for (; j < cnt; j++) {
            int2 e = se[j];
            float2 a = __half22float2(Bm[e.x + t]);
            float c = __int_as_float(e.y);
            accx = fmaf(a.x, c, accx);
            accy = fmaf(a.y, c, accy);
        }
    }

    int c0 = 2 * t, c1 = 2 * t + 1;
    float s0 = gg[c0] * rsqrtf(vv[c0] + EPSV);
    float s1 = gg[c1] * rsqrtf(vv[c1] + EPSV);
    float y0 = (accx + bias[c0] - mm[c0]) * s0 + bb[c0];
    float y1 = (accy + bias[c1] - mm[c1]) * s1 + bb[c1];
    if (FINAL) {
        ((float2*)outp)[i * NT + t] = make_float2(y0, y1);
    } else {
        float2* Ares = (float2*)g_A;
        float2 r = Ares[i * NT + t];
        r.x += fmaxf(y0, 0.0f);
        r.y += fmaxf(y1, 0.0f);
        Ares[i * NT + t] = r;
    }
}

// ---------------- host ----------------
extern "C" void kernel_launch(void* const* d_in, const int* in_sizes, int n_in,
                              void* d_out, int out_size) {
    const float* x    = (const float*)d_in[0];
    const int*   ei   = (const int*)d_in[1];   // int32! (JAX x64 disabled)
    const float* W_in = (const float*)d_in[2];
    const float* b_in = (const float*)d_in[3];
    const float* W0 = (const float*)d_in[4],  *b0 = (const float*)d_in[5];
    const float* g0 = (const float*)d_in[6],  *be0 = (const float*)d_in[7];
    const float* m0 = (const float*)d_in[8],  *v0 = (const float*)d_in[9];
    const float* W1 = (const float*)d_in[10], *b1 = (const float*)d_in[11];
    const float* g1 = (const float*)d_in[12], *be1 = (const float*)d_in[13];
    const float* m1 = (const float*)d_in[14], *v1 = (const float*)d_in[15];
    const float* W2 = (const float*)d_in[16], *b2 = (const float*)d_in[17];
    const float* g2 = (const float*)d_in[18], *be2 = (const float*)d_in[19];
    const float* m2 = (const float*)d_in[20], *v2 = (const float*)d_in[21];
    float* out = (float*)d_out;

    // dynamic smem sizes for the fp16 GEMMs (exceed 48KB static limit)
    const int SMEM_H = 128 * (HH + 8 + HH + 8) * (int)sizeof(__half);   // DO=128
    const int SMEM_D = 128 * (HH + 8 + DD + 8) * (int)sizeof(__half);   // DO=64
    cudaFuncSetAttribute(k_hgemm<HH>, cudaFuncAttributeMaxDynamicSharedMemorySize, SMEM_H);
    cudaFuncSetAttribute(k_hgemm<DD>, cudaFuncAttributeMaxDynamicSharedMemorySize, SMEM_D);

    // Fork: CSR build (depends only on edge_index) runs concurrently with
    // inproj + GEMM0 (depend only on x, W_in, W0). Join before agg layer 0.
    cudaStream_t s2;
    cudaStreamCreateWithFlags(&s2, cudaStreamNonBlocking);
    cudaEvent_t evFork, evJoin;
    cudaEventCreateWithFlags(&evFork, cudaEventDisableTiming);
    cudaEventCreateWithFlags(&evJoin, cudaEventDisableTiming);

    cudaEventRecord(evFork, 0);
    cudaStreamWaitEvent(s2, evFork, 0);

    // CSR chain on side stream
    k_zero_cnt<<<256, 256, 0, s2>>>();
    k_hist<<<1024, 256, 0, s2>>>(ei);
    k_scan_local<<<NBLK, SCAN_BS, 0, s2>>>();
    k_scan_blocks<<<1, 32, 0, s2>>>();
    k_scan_add<<<NBLK, SCAN_BS, 0, s2>>>();
    k_scatter<<<1024, 256, 0, s2>>>(ei);
    cudaEventRecord(evJoin, s2);

    // main stream: input projection + layer-0 GEMM
    k_inproj<<<NN, HH>>>(x, W_in, b_in);
    const int GB = (NN + 127) / 128;
    k_hgemm<HH><<<GB, 256, SMEM_H>>>(W0);

    // join: aggregation needs the CSR
    cudaStreamWaitEvent(0, evJoin, 0);

    // layer 0
    k_agg<HH, false><<<NN, HH / 2>>>(b0, g0, be0, m0, v0, nullptr);
    // layer 1
    k_hgemm<HH><<<GB, 256, SMEM_H>>>(W1);
    k_agg<HH, false><<<NN, HH / 2>>>(b1, g1, be1, m1, v1, nullptr);
    // layer 2 (final)
    k_hgemm<DD><<<GB, 256, SMEM_D>>>(W2);
    k_agg<DD, true><<<NN, DD / 2>>>(b2, g2, be2, m2, v2, out);
}